// round 12
// baseline (speedup 1.0000x reference)
#include <cuda_runtime.h>
#include <math.h>

// Problem constants
#define BB 64
#define SS 1024
#define HH 128
#define HHQ 32               // h per logits block (h-quarter)
#define AA 8
#define WIN 5
#define PADW 2
#define STILE 256            // s-tile for logits kernel
#define GROWS (STILE + 4)    // 260 padded rows in logits tile
#define CCH 128              // s per ctx block
#define NCH (SS / CCH)       // 8 coarse ctx chunks
#define RPW 1028             // ctx rbuf pitch (floats)
#define NCTXW 8              // ctx warps per block

// Scratch (no allocations allowed)
// Packed G: [h][w][8] with inner order (a0,a4,a1,a5,a2,a6,a3,a7) so a 16B load
// yields two 64-bit (G[a],G[a+4]) pairs for fma.rn.f32x2.
__device__ float4 gGp4[HH * WIN * 2];                // 128*5*8 floats
__device__ float gLogits[4 * AA * BB * SS];          // [hq][a][b][s] partials
__device__ float gCtxPart[NCH * AA * BB * HH];       // [sc][a][b][h]  (2.1MB)

__device__ __forceinline__ void fma2(unsigned long long& acc,
                                     unsigned long long d2,
                                     unsigned long long g2) {
    asm("fma.rn.f32x2 %0, %1, %2, %3;" : "=l"(acc) : "l"(d2), "l"(g2), "l"(acc));
}
__device__ __forceinline__ unsigned long long dup2(float v) {
    unsigned long long r;
    asm("mov.b64 %0, {%1, %1};" : "=l"(r) : "f"(v));
    return r;
}
__device__ __forceinline__ unsigned long long pk2(float lo, float hi) {
    unsigned long long r;
    asm("mov.b64 %0, {%1, %2};" : "=l"(r) : "f"(lo), "f"(hi));
    return r;
}
__device__ __forceinline__ void unpk(unsigned long long p, float& lo, float& hi) {
    asm("mov.b64 {%0, %1}, %2;" : "=f"(lo), "=f"(hi) : "l"(p));
}

// ---------------------------------------------------------------------------
// K1: G[a,h,w] = sum_f P[a,h,f] * E[a,f,w]; packed scatter to gGp4.
// grid = (A, 4), block = 128. thread: h = hg*32 + (t>>2), f-quarter q = t&3.
// ---------------------------------------------------------------------------
__global__ void k_prep(const float* __restrict__ P, const float* __restrict__ E) {
    __shared__ float Esm[HH * WIN];
    int a = blockIdx.x, hg = blockIdx.y, t = threadIdx.x;
    int h = hg * 32 + (t >> 2), q = t & 3;

    for (int i = t; i < HH * WIN; i += 128)
        Esm[i] = E[(size_t)a * HH * WIN + i];
    __syncthreads();

    const float4* Pp = (const float4*)(P + (size_t)a * HH * HH + h * HH + q * 32);
    float g[WIN] = {0.f, 0.f, 0.f, 0.f, 0.f};
    #pragma unroll
    for (int i = 0; i < 8; ++i) {
        float4 p = Pp[i];
        int f0 = q * 32 + i * 4;
        #pragma unroll
        for (int w = 0; w < WIN; ++w) {
            g[w] += p.x * Esm[(f0 + 0) * WIN + w];
            g[w] += p.y * Esm[(f0 + 1) * WIN + w];
            g[w] += p.z * Esm[(f0 + 2) * WIN + w];
            g[w] += p.w * Esm[(f0 + 3) * WIN + w];
        }
    }
    #pragma unroll
    for (int w = 0; w < WIN; ++w) {
        g[w] += __shfl_xor_sync(0xffffffffu, g[w], 1);
        g[w] += __shfl_xor_sync(0xffffffffu, g[w], 2);
    }
    if (q == 0) {
        float* Gp = (float*)gGp4;
        #pragma unroll
        for (int w = 0; w < WIN; ++w)
            Gp[(h * WIN + w) * 8 + (a & 3) * 2 + (a >> 2)] = g[w];
    }
}

// ---------------------------------------------------------------------------
// K2 v5: logits partial over one h-quarter, 8 s per lane.
// gLogits[hq][a][b][s] = sum_w sum_{h in quarter} doc[b,s+w-2,h] * G[a,h,w]
// Per h-iter/warp: 12 scalar taps + 10 G LDS.128 feed 160 FFMA2.
// dsm [GROWS][32], swizzle col = h ^ ((row>>3)&31): taps at rows 8*lane+r hit
// distinct banks (bijection in lane); fill (row const) trivially c-free.
// grid = (S/256, B, 4), block = 128 (warp -> 8-h split of the quarter).
// ---------------------------------------------------------------------------
__global__ void __launch_bounds__(128) k_logits(const float* __restrict__ doc) {
    extern __shared__ float sm[];
    float* dsm = sm;                          // [GROWS][32] swizzled (33.3KB)
    float* Gsm = sm + GROWS * HHQ;            // [32*WIN*8] packed pairs (5.1KB)
    int b  = blockIdx.y;
    int s0 = blockIdx.x * STILE;
    int hq = blockIdx.z;
    int t  = threadIdx.x;
    int wid = t >> 5, lane = t & 31;

    {   // Copy this quarter's packed G (1280 floats = 320 float4)
        const float4* src = gGp4 + (size_t)hq * HHQ * WIN * 2;
        float4* dst = (float4*)Gsm;
        #pragma unroll
        for (int i = t; i < HHQ * WIN * 2; i += 128) dst[i] = src[i];
    }

    // Tile fill: one row per warp-iter; lane loads 1 float (128B coalesced),
    // scalar swizzled store (conflict-free: distinct cols per lane).
    const float* db = doc + ((size_t)b * SS) * HH + hq * HHQ;
    for (int row = wid; row < GROWS; row += 4) {
        int gs = s0 - PADW + row;
        float v = (gs >= 0 && gs < SS) ? db[(size_t)gs * HH + lane] : 0.f;
        dsm[row * HHQ + (lane ^ ((row >> 3) & 31))] = v;
    }
    __syncthreads();

    int h0 = wid * 8;                         // warp's 8 local h
    int st0 = 8 * lane;                       // lane's 8 consecutive s
    unsigned long long acc[8][4];
    #pragma unroll
    for (int i = 0; i < 8; ++i)
        #pragma unroll
        for (int p = 0; p < 4; ++p) acc[i][p] = 0ull;

    #pragma unroll 2
    for (int hh = 0; hh < 8; ++hh) {
        int h = h0 + hh;                      // local h in [0,32)
        unsigned long long d[12];
        #pragma unroll
        for (int r = 0; r < 12; ++r) {
            int row = st0 + r;
            d[r] = dup2(dsm[row * HHQ + (h ^ ((row >> 3) & 31))]);
        }
        const float* gh = &Gsm[h * (WIN * 8)];
        #pragma unroll
        for (int w = 0; w < WIN; ++w) {
            ulonglong2 g01 = *(const ulonglong2*)(gh + w * 8);
            ulonglong2 g23 = *(const ulonglong2*)(gh + w * 8 + 4);
            #pragma unroll
            for (int si = 0; si < 8; ++si) {
                fma2(acc[si][0], d[si + w], g01.x);
                fma2(acc[si][1], d[si + w], g01.y);
                fma2(acc[si][2], d[si + w], g23.x);
                fma2(acc[si][3], d[si + w], g23.y);
            }
        }
    }

    // Cross-warp h-reduction: red[st][33], slot = a*4 + wid.
    __syncthreads();
    float* red = sm;   // 256*33 = 8448 floats (33.8KB), fits in smem block
    #pragma unroll
    for (int si = 0; si < 8; ++si) {
        int st = st0 + si;
        #pragma unroll
        for (int p = 0; p < 4; ++p) {
            float lo, hi;
            unpk(acc[si][p], lo, hi);
            red[st * 33 + p * 4 + wid] = lo;           // aspect p
            red[st * 33 + (p + 4) * 4 + wid] = hi;     // aspect p+4
        }
    }
    __syncthreads();

    #pragma unroll
    for (int half = 0; half < 2; ++half) {
        int st = half * 128 + t;
        #pragma unroll
        for (int a = 0; a < AA; ++a) {
            const float* rp = &red[st * 33 + a * 4];
            float v = rp[0] + rp[1] + rp[2] + rp[3];
            gLogits[(((size_t)hq * AA + a) * BB + b) * SS + s0 + st] = v;
        }
    }
}

// ---------------------------------------------------------------------------
// K3: attn = softmax_s(sum of 4 h-quarter partials); write to out[b][a][s]
// grid = A*B (row = a*B + b), block = 256
// ---------------------------------------------------------------------------
__global__ void k_softmax(float* __restrict__ out) {
    int row = blockIdx.x;
    int a = row >> 6;
    int b = row & 63;
    const float* lg = gLogits + (size_t)row * SS;
    const size_t QOFF = (size_t)AA * BB * SS;
    int t = threadIdx.x;

    float v[4];
    float m = -3.4e38f;
    #pragma unroll
    for (int i = 0; i < 4; ++i) {
        int s = t + i * 256;
        v[i] = (lg[s] + lg[QOFF + s]) + (lg[2 * QOFF + s] + lg[3 * QOFF + s]);
        m = fmaxf(m, v[i]);
    }

    __shared__ float redm[8];
    #pragma unroll
    for (int o = 16; o > 0; o >>= 1) m = fmaxf(m, __shfl_xor_sync(0xffffffffu, m, o));
    if ((t & 31) == 0) redm[t >> 5] = m;
    __syncthreads();
    m = redm[0];
    #pragma unroll
    for (int i = 1; i < 8; ++i) m = fmaxf(m, redm[i]);

    float sl = 0.f;
    #pragma unroll
    for (int i = 0; i < 4; ++i) { v[i] = __expf(v[i] - m); sl += v[i]; }
    __shared__ float reds[8];
    #pragma unroll
    for (int o = 16; o > 0; o >>= 1) sl += __shfl_xor_sync(0xffffffffu, sl, o);
    if ((t & 31) == 0) reds[t >> 5] = sl;
    __syncthreads();
    float tot = 0.f;
    #pragma unroll
    for (int i = 0; i < 8; ++i) tot += reds[i];
    float inv = 1.0f / tot;

    float* op = out + ((size_t)b * AA + a) * SS;
    #pragma unroll
    for (int i = 0; i < 4; ++i) op[t + i * 256] = v[i] * inv;
}

// ---------------------------------------------------------------------------
// K4: ctx partials — R7 design at 256 threads (8 warps x 16 s of a 128-chunk)
// for 2x in-flight loads. Warp w owns s in [w*16, w*16+16); lane = h-quad
// (LDG.128, 512B/warp-inst). 8-warp smem reduce, coalesced store.
// grid = (B, 8), block = 256.
// ---------------------------------------------------------------------------
__global__ void __launch_bounds__(256) k_ctx(const float* __restrict__ doc,
                                             const float* __restrict__ attn) {
    int b = blockIdx.x, sc = blockIdx.y;
    int t = threadIdx.x, w = t >> 5, lane = t & 31;

    __shared__ float asmem[AA * CCH];         // 4KB
    __shared__ float rbuf[NCTXW * RPW];       // 32.9KB
    #pragma unroll
    for (int i = t; i < AA * CCH; i += 256) {
        int a = i >> 7, s = i & 127;
        asmem[i] = attn[((size_t)b * AA + a) * SS + sc * CCH + s];
    }
    __syncthreads();

    const float4* dp = (const float4*)(doc + ((size_t)b * SS + sc * CCH) * HH) + lane;
    unsigned long long acc[AA][2];
    #pragma unroll
    for (int a = 0; a < AA; ++a) { acc[a][0] = 0ull; acc[a][1] = 0ull; }

    int sb = w * 16;
    #pragma unroll 8
    for (int i = 0; i < 16; ++i) {
        int s = sb + i;
        float4 dv = dp[s * 32];                    // coalesced 512B/warp LDG.128
        unsigned long long dxy = pk2(dv.x, dv.y);
        unsigned long long dzw = pk2(dv.z, dv.w);
        #pragma unroll
        for (int a = 0; a < AA; ++a) {
            unsigned long long av = dup2(asmem[a * CCH + s]);   // broadcast
            fma2(acc[a][0], dxy, av);
            fma2(acc[a][1], dzw, av);
        }
    }

    #pragma unroll
    for (int a = 0; a < AA; ++a) {
        float4 o;
        unpk(acc[a][0], o.x, o.y);
        unpk(acc[a][1], o.z, o.w);
        *(float4*)&rbuf[w * RPW + a * HH + lane * 4] = o;   // conflict-free STS.128
    }
    __syncthreads();

    // Reduce over the 8 warps: entry e = k*256 + t -> (a = e>>7, h = e&127).
    #pragma unroll
    for (int k = 0; k < 4; ++k) {
        int e = k * 256 + t;
        int a = e >> 7, h = e & 127;
        int slot = a * HH + h;
        float v = ((rbuf[slot] + rbuf[RPW + slot]) +
                   (rbuf[2 * RPW + slot] + rbuf[3 * RPW + slot])) +
                  ((rbuf[4 * RPW + slot] + rbuf[5 * RPW + slot]) +
                   (rbuf[6 * RPW + slot] + rbuf[7 * RPW + slot]));
        gCtxPart[(((size_t)sc * AA + a) * BB + b) * HH + h] = v;   // coalesced
    }
}

// ---------------------------------------------------------------------------
// K5: rep[b,a,f] = sum_h ctx[a,b,h] * P[a,h,f], ctx reduced over 8 partials
// grid = B*A (blk = b*A + a), block = 128 (thread = f)
// ---------------------------------------------------------------------------
__global__ void k_rep(const float* __restrict__ P, float* __restrict__ out) {
    int blk = blockIdx.x;
    int a = blk & 7, b = blk >> 3;
    int f = threadIdx.x;
    __shared__ float csm[HH];
    float c = 0.f;
    #pragma unroll
    for (int sc = 0; sc < NCH; ++sc)
        c += gCtxPart[(((size_t)sc * AA + a) * BB + b) * HH + f];
    csm[f] = c;
    __syncthreads();

    float acc = 0.f;
    const float* Pp = P + (size_t)a * HH * HH + f;
    #pragma unroll 8
    for (int h = 0; h < HH; ++h) acc += csm[h] * Pp[(size_t)h * HH];

    out[(size_t)BB * AA * SS + ((size_t)b * AA + a) * HH + f] = acc;
}

// ---------------------------------------------------------------------------
extern "C" void kernel_launch(void* const* d_in, const int* in_sizes, int n_in,
                              void* d_out, int out_size) {
    const float* doc = (const float*)d_in[0];   // (B,S,H)
    const float* E   = (const float*)d_in[1];   // (A, WIN*H)
    const float* P   = (const float*)d_in[2];   // (A,H,H)
    float* out = (float*)d_out;                 // [attn (B,A,S) | rep (B,A,H)]

    size_t sm2 = (size_t)(GROWS * HHQ + HHQ * WIN * 8) * sizeof(float);  // ~38.4 KB
    cudaFuncSetAttribute(k_logits, cudaFuncAttributeMaxDynamicSharedMemorySize, (int)sm2);

    k_prep<<<dim3(AA, 4), 128>>>(P, E);
    k_logits<<<dim3(SS / STILE, BB, 4), 128, sm2>>>(doc);
    k_softmax<<<AA * BB, 256>>>(out);
    k_ctx<<<dim3(BB, NCH), 256>>>(doc, out);
    k_rep<<<BB * AA, 128>>>(P, out);
}

// round 16
// speedup vs baseline: 1.7432x; 1.7432x over previous
#include <cuda_runtime.h>
#include <math.h>
#include <float.h>

// Problem constants
#define BB 64
#define SS 1024
#define HH 128
#define HHF 64               // h per logits block (h-split)
#define AA 8
#define WIN 5
#define PADW 2
#define STILE 128            // s-tile for logits kernel
#define GROWS (STILE + 4)    // 132 padded rows in logits tile
#define RPW 1028             // ctx rbuf pitch (floats)

// Scratch (no allocations allowed)
__device__ float4 gGp4[HH * WIN * 2];                // packed G
__device__ float gLogits[2 * AA * BB * SS];          // [hb][a][b][s] partials
__device__ float gCtxPart[2 * AA * BB * HH];         // [half][a][b][h] (0.5MB)

__device__ __forceinline__ void fma2(unsigned long long& acc,
                                     unsigned long long d2,
                                     unsigned long long g2) {
    asm("fma.rn.f32x2 %0, %1, %2, %3;" : "=l"(acc) : "l"(d2), "l"(g2), "l"(acc));
}
__device__ __forceinline__ unsigned long long dup2(float v) {
    unsigned long long r;
    asm("mov.b64 %0, {%1, %1};" : "=l"(r) : "f"(v));
    return r;
}
__device__ __forceinline__ unsigned long long pk2(float lo, float hi) {
    unsigned long long r;
    asm("mov.b64 %0, {%1, %2};" : "=l"(r) : "f"(lo), "f"(hi));
    return r;
}
__device__ __forceinline__ void unpk(unsigned long long p, float& lo, float& hi) {
    asm("mov.b64 {%0, %1}, %2;" : "=f"(lo), "=f"(hi) : "l"(p));
}

// ---------------------------------------------------------------------------
// K1: G[a,h,w] = sum_f P[a,h,f] * E[a,f,w]; packed scatter to gGp4. (R11)
// ---------------------------------------------------------------------------
__global__ void k_prep(const float* __restrict__ P, const float* __restrict__ E) {
    __shared__ float Esm[HH * WIN];
    int a = blockIdx.x, hg = blockIdx.y, t = threadIdx.x;
    int h = hg * 32 + (t >> 2), q = t & 3;

    for (int i = t; i < HH * WIN; i += 128)
        Esm[i] = E[(size_t)a * HH * WIN + i];
    __syncthreads();

    const float4* Pp = (const float4*)(P + (size_t)a * HH * HH + h * HH + q * 32);
    float g[WIN] = {0.f, 0.f, 0.f, 0.f, 0.f};
    #pragma unroll
    for (int i = 0; i < 8; ++i) {
        float4 p = Pp[i];
        int f0 = q * 32 + i * 4;
        #pragma unroll
        for (int w = 0; w < WIN; ++w) {
            g[w] += p.x * Esm[(f0 + 0) * WIN + w];
            g[w] += p.y * Esm[(f0 + 1) * WIN + w];
            g[w] += p.z * Esm[(f0 + 2) * WIN + w];
            g[w] += p.w * Esm[(f0 + 3) * WIN + w];
        }
    }
    #pragma unroll
    for (int w = 0; w < WIN; ++w) {
        g[w] += __shfl_xor_sync(0xffffffffu, g[w], 1);
        g[w] += __shfl_xor_sync(0xffffffffu, g[w], 2);
    }
    if (q == 0) {
        float* Gp = (float*)gGp4;
        #pragma unroll
        for (int w = 0; w < WIN; ++w)
            Gp[(h * WIN + w) * 8 + (a & 3) * 2 + (a >> 2)] = g[w];
    }
}

// ---------------------------------------------------------------------------
// K2: logits partial over one h-half (R11-proven, VERBATIM).
// grid = (S/128, B, 2), block = 128, smem 44KB.
// ---------------------------------------------------------------------------
__global__ void __launch_bounds__(128) k_logits(const float* __restrict__ doc) {
    extern __shared__ float sm[];
    float* dsm = sm;                         // [GROWS][64] swizzled
    float* Gsm = sm + GROWS * HHF;           // [64*WIN*8] packed pairs (half)
    int b  = blockIdx.y;
    int s0 = blockIdx.x * STILE;
    int hb = blockIdx.z;
    int t  = threadIdx.x;
    int wid = t >> 5, lane = t & 31;

    {   // Copy this half's packed G
        const float4* src = gGp4 + (size_t)hb * HHF * WIN * 2;
        float4* dst = (float4*)Gsm;
        #pragma unroll
        for (int i = t; i < HHF * WIN * 2; i += 128) dst[i] = src[i];
    }

    const float* db = doc + ((size_t)b * SS) * HH + hb * HHF;
    for (int row = wid; row < GROWS; row += 4) {
        int gs = s0 - PADW + row;
        int swz = (row >> 2) & 31;
        float2 v = make_float2(0.f, 0.f);
        if (gs >= 0 && gs < SS)
            v = *((const float2*)(db + (size_t)gs * HH) + lane);
        int c = 2 * lane;
        dsm[row * HHF + ((c + 0) ^ swz)] = v.x;
        dsm[row * HHF + ((c + 1) ^ swz)] = v.y;
    }
    __syncthreads();

    int h0 = wid * 16;
    int st0 = 4 * lane;
    unsigned long long acc[4][4];
    #pragma unroll
    for (int i = 0; i < 4; ++i)
        #pragma unroll
        for (int p = 0; p < 4; ++p) acc[i][p] = 0ull;

    #pragma unroll 2
    for (int hh = 0; hh < 16; ++hh) {
        int h = h0 + hh;
        unsigned long long d[8];
        #pragma unroll
        for (int r = 0; r < 8; ++r) {
            int row = st0 + r;
            d[r] = dup2(dsm[row * HHF + (h ^ ((row >> 2) & 31))]);
        }
        const float* gh = &Gsm[h * (WIN * 8)];
        #pragma unroll
        for (int w = 0; w < WIN; ++w) {
            ulonglong2 g01 = *(const ulonglong2*)(gh + w * 8);
            ulonglong2 g23 = *(const ulonglong2*)(gh + w * 8 + 4);
            #pragma unroll
            for (int si = 0; si < 4; ++si) {
                fma2(acc[si][0], d[si + w], g01.x);
                fma2(acc[si][1], d[si + w], g01.y);
                fma2(acc[si][2], d[si + w], g23.x);
                fma2(acc[si][3], d[si + w], g23.y);
            }
        }
    }

    __syncthreads();
    float* red = sm;
    #pragma unroll
    for (int si = 0; si < 4; ++si) {
        int st = st0 + si;
        #pragma unroll
        for (int p = 0; p < 4; ++p) {
            float lo, hi;
            unpk(acc[si][p], lo, hi);
            red[st * 33 + p * 4 + wid] = lo;
            red[st * 33 + (p + 4) * 4 + wid] = hi;
        }
    }
    __syncthreads();

    int st = t;
    #pragma unroll
    for (int a = 0; a < AA; ++a) {
        const float* rp = &red[st * 33 + a * 4];
        float v = rp[0] + rp[1] + rp[2] + rp[3];
        gLogits[(((size_t)hb * AA + a) * BB + b) * SS + s0 + st] = v;
    }
}

// ---------------------------------------------------------------------------
// K3 (fused softmax + ctx): grid = (B, 2), block = 512 (16 warps).
// Phase 1: load+sum logit halves into smem buf[8][1024], row max/exp/sum,
//          write attn out for this block's s-half.
// Phase 2: R7-proven ctx pattern over this half's 512 s (warp = 32 s,
//          lane = h-quad LDG.128, f32x2 acc, raw-exp weights, inv folded at
//          the end). 16-warp reduce via two 8-warp rbuf stages.
// smem: 8192 (buf) + 8*RPW (rbuf) + 48 (stats) floats = ~65.9KB dynamic.
// ---------------------------------------------------------------------------
__global__ void __launch_bounds__(512) k_ctxsm(const float* __restrict__ doc,
                                               float* __restrict__ out) {
    extern __shared__ float sm[];
    float* buf  = sm;                    // [8][1024] raw logits -> exp
    float* rbuf = sm + AA * SS;          // [8][RPW]
    float* stat = rbuf + 8 * RPW;        // warpmax[16] rowmax[8] wsum[16] inv[8]
    int b = blockIdx.x, half = blockIdx.y;
    int t = threadIdx.x, w = t >> 5, lane = t & 31;

    // Load both h-half logit partials, summed (coalesced).
    const size_t HOFF = (size_t)AA * BB * SS;
    #pragma unroll
    for (int i = 0; i < 16; ++i) {
        int idx = t + 512 * i;           // a = idx>>10, s = idx&1023
        int a = idx >> 10, s = idx & 1023;
        size_t off = ((size_t)a * BB + b) * SS + s;
        buf[idx] = gLogits[off] + gLogits[HOFF + off];
    }
    __syncthreads();

    // Row max: warp w -> row a = w>>1, s-segment (w&1)*512.
    {
        int a = w >> 1, sb = (w & 1) * 512;
        float m = -FLT_MAX;
        #pragma unroll
        for (int j = 0; j < 16; ++j) m = fmaxf(m, buf[a * SS + sb + lane + 32 * j]);
        #pragma unroll
        for (int o = 16; o > 0; o >>= 1) m = fmaxf(m, __shfl_xor_sync(0xffffffffu, m, o));
        if (lane == 0) stat[w] = m;
    }
    __syncthreads();
    if (t < 8) stat[16 + t] = fmaxf(stat[2 * t], stat[2 * t + 1]);
    __syncthreads();

    // exp + row sum (in place).
    {
        int a = w >> 1, sb = (w & 1) * 512;
        float m = stat[16 + a];
        float sum = 0.f;
        #pragma unroll
        for (int j = 0; j < 16; ++j) {
            int ix = a * SS + sb + lane + 32 * j;
            float e = __expf(buf[ix] - m);
            buf[ix] = e;
            sum += e;
        }
        #pragma unroll
        for (int o = 16; o > 0; o >>= 1) sum += __shfl_xor_sync(0xffffffffu, sum, o);
        if (lane == 0) stat[24 + w] = sum;
    }
    __syncthreads();
    if (t < 8) stat[40 + t] = 1.0f / (stat[24 + 2 * t] + stat[24 + 2 * t + 1]);
    __syncthreads();

    // Write attn for this block's s-half: warp w -> row a=w>>1, 256-s segment.
    {
        int a = w >> 1;
        float inv = stat[40 + a];
        int sb = half * 512 + (w & 1) * 256;
        float* op = out + ((size_t)b * AA + a) * SS + sb;
        #pragma unroll
        for (int j = 0; j < 8; ++j)
            op[lane + 32 * j] = buf[a * SS + sb + lane + 32 * j] * inv;
    }
    __syncthreads();

    // ctx phase (R7 pattern): warp w owns s_local in [w*32, w*32+32).
    const float4* dp = (const float4*)(doc + ((size_t)b * SS + half * 512) * HH) + lane;
    unsigned long long acc[AA][2];
    #pragma unroll
    for (int a = 0; a < AA; ++a) { acc[a][0] = 0ull; acc[a][1] = 0ull; }

    int sb = w * 32;
    #pragma unroll 8
    for (int i = 0; i < 32; ++i) {
        int s = sb + i;
        float4 dv = dp[s * 32];                    // coalesced 512B/warp LDG.128
        unsigned long long dxy = pk2(dv.x, dv.y);
        unsigned long long dzw = pk2(dv.z, dv.w);
        int sg = half * 512 + s;
        #pragma unroll
        for (int a = 0; a < AA; ++a) {
            unsigned long long av = dup2(buf[a * SS + sg]);   // broadcast
            fma2(acc[a][0], dxy, av);
            fma2(acc[a][1], dzw, av);
        }
    }

    // 16-warp reduce: stage 1 (warps 0-7 write), stage 2 (8-15 add).
    if (w < 8) {
        #pragma unroll
        for (int a = 0; a < AA; ++a) {
            float4 o;
            unpk(acc[a][0], o.x, o.y);
            unpk(acc[a][1], o.z, o.w);
            *(float4*)&rbuf[w * RPW + a * HH + lane * 4] = o;
        }
    }
    __syncthreads();
    if (w >= 8) {
        float* rb = &rbuf[(w - 8) * RPW];
        #pragma unroll
        for (int a = 0; a < AA; ++a) {
            float4 o = *(float4*)&rb[a * HH + lane * 4];
            float lo, hi;
            unpk(acc[a][0], lo, hi); o.x += lo; o.y += hi;
            unpk(acc[a][1], lo, hi); o.z += lo; o.w += hi;
            *(float4*)&rb[a * HH + lane * 4] = o;
        }
    }
    __syncthreads();

    // Final: 1024 entries over 512 threads; fold inv[a]; coalesced store.
    #pragma unroll
    for (int k = 0; k < 2; ++k) {
        int e = k * 512 + t;
        int a = e >> 7, h = e & 127;
        int slot = a * HH + h;
        float v = ((rbuf[slot] + rbuf[RPW + slot]) +
                   (rbuf[2 * RPW + slot] + rbuf[3 * RPW + slot])) +
                  ((rbuf[4 * RPW + slot] + rbuf[5 * RPW + slot]) +
                   (rbuf[6 * RPW + slot] + rbuf[7 * RPW + slot]));
        v *= stat[40 + a];
        gCtxPart[(((size_t)half * AA + a) * BB + b) * HH + h] = v;
    }
}

// ---------------------------------------------------------------------------
// K4: rep[b,a,f] = sum_h ctx[a,b,h] * P[a,h,f], ctx reduced over 2 partials
// grid = B*A (blk = b*A + a), block = 128 (thread = f)
// ---------------------------------------------------------------------------
__global__ void k_rep(const float* __restrict__ P, float* __restrict__ out) {
    int blk = blockIdx.x;
    int a = blk & 7, b = blk >> 3;
    int f = threadIdx.x;
    __shared__ float csm[HH];
    float c = gCtxPart[(((size_t)0 * AA + a) * BB + b) * HH + f] +
              gCtxPart[(((size_t)1 * AA + a) * BB + b) * HH + f];
    csm[f] = c;
    __syncthreads();

    float acc = 0.f;
    const float* Pp = P + (size_t)a * HH * HH + f;
    #pragma unroll 8
    for (int h = 0; h < HH; ++h) acc += csm[h] * Pp[(size_t)h * HH];

    out[(size_t)BB * AA * SS + ((size_t)b * AA + a) * HH + f] = acc;
}

// ---------------------------------------------------------------------------
extern "C" void kernel_launch(void* const* d_in, const int* in_sizes, int n_in,
                              void* d_out, int out_size) {
    const float* doc = (const float*)d_in[0];   // (B,S,H)
    const float* E   = (const float*)d_in[1];   // (A, WIN*H)
    const float* P   = (const float*)d_in[2];   // (A,H,H)
    float* out = (float*)d_out;                 // [attn (B,A,S) | rep (B,A,H)]

    size_t sm2 = (size_t)(GROWS * HHF + HHF * WIN * 8) * sizeof(float);   // ~44 KB
    size_t sm3 = (size_t)(AA * SS + 8 * RPW + 48) * sizeof(float);        // ~65.9 KB
    cudaFuncSetAttribute(k_logits, cudaFuncAttributeMaxDynamicSharedMemorySize, (int)sm2);
    cudaFuncSetAttribute(k_ctxsm,  cudaFuncAttributeMaxDynamicSharedMemorySize, (int)sm3);

    k_prep<<<dim3(AA, 4), 128>>>(P, E);
    k_logits<<<dim3(SS / STILE, BB, 2), 128, sm2>>>(doc);
    k_ctxsm<<<dim3(BB, 2), 512, sm3>>>(doc, out);
    k_rep<<<BB * AA, 128>>>(P, out);
}